// round 16
// baseline (speedup 1.0000x reference)
#include <cuda_runtime.h>
#include <cuda_fp16.h>
#include <cstdint>

// R16: split-K x split-E warp layout. CTA = 16 tok, 4 warps = (wk,we):
// wk = K-half (one ks16 per 32k-chunk each), we = 32-expert half.
// Halves redundant A-LDSM traffic (was 4 warps x same fragments).
// Epilogue: wk=0 writes Cs, wk=1 adds (barrier-ordered, columns disjoint
// per we). Same fp16 2-term split numerics, fold every 2 chunks.
// Output: [T*8 idx as float | T*8 weights].

#define MMAH(d, a, b0, b1)                                                    \
    asm volatile("mma.sync.aligned.m16n8k16.row.col.f32.f16.f16.f32 "         \
                 "{%0,%1,%2,%3}, {%4,%5,%6,%7}, {%8,%9}, {%0,%1,%2,%3};"      \
                 : "+f"((d)[0]), "+f"((d)[1]), "+f"((d)[2]), "+f"((d)[3])     \
                 : "r"((a)[0]), "r"((a)[1]), "r"((a)[2]), "r"((a)[3]),        \
                   "r"(b0), "r"(b1))

#define LDSM4(r0, r1, r2, r3, addr)                                           \
    asm volatile("ldmatrix.sync.aligned.m8n8.x4.shared.b16 {%0,%1,%2,%3}, [%4];" \
                 : "=r"(r0), "=r"(r1), "=r"(r2), "=r"(r3) : "r"(addr))

#define CVTPKH(d, lo, hi)                                                     \
    asm("cvt.rn.f16x2.f32 %0, %1, %2;" : "=r"(d) : "f"(hi), "f"(lo))

// B fragments: [ks(128)][term(2)][npair(4)][lane(32)] x uint4 = 512 KB
__device__ __align__(16) uint4 g_Bf[128 * 2 * 4 * 32];

static __device__ __forceinline__ void splitpairh(float lo, float hi,
                                                  uint32_t& o1, uint32_t& o2) {
    CVTPKH(o1, lo, hi);
    __half2 h = *reinterpret_cast<__half2*>(&o1);
    float2 b = __half22float2(h);
    float l1 = lo - b.x;
    float h1 = hi - b.y;
    CVTPKH(o2, l1, h1);
}

__global__ void w_split_kernel(const float* __restrict__ W) {
    int idx  = blockIdx.x * 256 + threadIdx.x;   // 0..16383
    int lane = idx & 31;
    int j    = (idx >> 5) & 3;                   // npair: experts j*16..j*16+15
    int ks   = idx >> 7;                         // k16 step 0..127
    int e_lo = j * 16 + (lane >> 2);
    int k    = ks * 16 + (lane & 3) * 2;

    const float* p = W + (size_t)e_lo * 2048 + k;
    float2 f0 = *(const float2*)p;
    float2 f1 = *(const float2*)(p + 8);
    float2 f2 = *(const float2*)(p + 8 * 2048);
    float2 f3 = *(const float2*)(p + 8 * 2048 + 8);

    uint4 q1, q2;
    splitpairh(f0.x, f0.y, q1.x, q2.x);
    splitpairh(f1.x, f1.y, q1.y, q2.y);
    splitpairh(f2.x, f2.y, q1.z, q2.z);
    splitpairh(f3.x, f3.y, q1.w, q2.w);
    g_Bf[((ks * 2 + 0) * 4 + j) * 32 + lane] = q1;
    g_Bf[((ks * 2 + 1) * 4 + j) * 32 + lane] = q2;
}

// smem: A tiles [buf(2)][term(2)][16 rows x 80B] = 5120 B; Cs overlays it.
#define TERM_BT 1280
#define BUF_BT  2560

__global__ __launch_bounds__(128, 5) void moe_gate_mma(
    const float* __restrict__ X,
    const float* __restrict__ bias,
    float* __restrict__ out,
    int w_off)
{
    __shared__ union {
        char  tiles[2 * BUF_BT];
        float Cs[16][65];
    } sm;

    const int tid  = threadIdx.x;
    const int lane = tid & 31;
    const int wid  = tid >> 5;           // 0..3
    const int wk   = wid & 1;            // K half: this warp's ks within a chunk
    const int we   = wid >> 1;           // expert half (32 experts)
    const int tok0 = blockIdx.x * 16;

    uint32_t sb;
    asm("{ .reg .u64 t; cvta.to.shared.u64 t, %1; cvt.u32.u64 %0, t; }"
        : "=r"(sb) : "l"(sm.tiles));

    // A gmem loader: row = tid>>3 (0..15), k-off = (tid&7)*4 floats
    const int arow = tid >> 3;
    const int akf  = (tid & 7) * 4;
    const float* aP = X + (size_t)(tok0 + arow) * 2048 + akf;
    const int stOff = arow * 80 + akf * 2;         // byte offset in a term tile

    // B fragment pointer
    const uint4* bP = g_Bf + lane;

    // A LDSM lane offsets (16-row m-tile)
    const int a_r  = (lane & 7) + ((lane >> 3) & 1) * 8;
    const int a_kb = ((lane >> 4) & 1) * 16;

    // acc index p = 2*pj + tile8 (pj = local npair 0..1, tile8 = n8 tile 0..1)
    float s_[4][4], cr[4][4];
    #pragma unroll
    for (int p = 0; p < 4; ++p)
        #pragma unroll
        for (int i = 0; i < 4; ++i) { s_[p][i] = 0.0f; cr[p][i] = 0.0f; }

    // ---- chunk 0: load + split + store buf 0 ----
    {
        float4 p0 = *(const float4*)(aP);
        uint32_t o1[2], o2[2];
        splitpairh(p0.x, p0.y, o1[0], o2[0]);
        splitpairh(p0.z, p0.w, o1[1], o2[1]);
        char* b0 = sm.tiles + stOff;
        *(uint2*)(b0)           = make_uint2(o1[0], o1[1]);
        *(uint2*)(b0 + TERM_BT) = make_uint2(o2[0], o2[1]);
    }
    // initial B fragments for this warp's ks (ksg = wk): [term][pj]
    uint4 Bc[2][2];
    #pragma unroll
    for (int t = 0; t < 2; ++t)
        #pragma unroll
        for (int pj = 0; pj < 2; ++pj)
            Bc[t][pj] = bP[wk * 256 + t * 128 + (2 * we + pj) * 32];
    __syncthreads();

    float4 pa0;
    #pragma unroll 1
    for (int c = 0; c < 64; ++c) {
        const int cur = c & 1;
        if (c < 63)                                // prefetch A chunk c+1
            pa0 = *(const float4*)(aP + (c + 1) * 32);

        // prefetch next chunk's B fragments (this warp's ks)
        const int kn = (2 * c + 2 + wk < 128) ? 2 * c + 2 + wk : 127;
        uint4 Bn[2][2];
        #pragma unroll
        for (int t = 0; t < 2; ++t)
            #pragma unroll
            for (int pj = 0; pj < 2; ++pj)
                Bn[t][pj] = bP[kn * 256 + t * 128 + (2 * we + pj) * 32];

        // A fragments: 2 terms at this warp's ks (wk)
        uint32_t af[2][4];
        #pragma unroll
        for (int t = 0; t < 2; ++t) {
            uint32_t ad = sb + cur * BUF_BT + t * TERM_BT
                        + a_r * 80 + a_kb + wk * 32;
            LDSM4(af[t][0], af[t][1], af[t][2], af[t][3], ad);
        }
        // 3 combos x 4 n-tiles = 12 MMA, all into cr
        #pragma unroll
        for (int pj = 0; pj < 2; ++pj) {
            MMAH(cr[2 * pj],     af[0], Bc[0][pj].x, Bc[0][pj].y);
            MMAH(cr[2 * pj + 1], af[0], Bc[0][pj].z, Bc[0][pj].w);

            MMAH(cr[2 * pj],     af[0], Bc[1][pj].x, Bc[1][pj].y);
            MMAH(cr[2 * pj + 1], af[0], Bc[1][pj].z, Bc[1][pj].w);

            MMAH(cr[2 * pj],     af[1], Bc[0][pj].x, Bc[0][pj].y);
            MMAH(cr[2 * pj + 1], af[1], Bc[0][pj].z, Bc[0][pj].w);
        }
        #pragma unroll
        for (int t = 0; t < 2; ++t)
            #pragma unroll
            for (int pj = 0; pj < 2; ++pj)
                Bc[t][pj] = Bn[t][pj];

        if (c & 1) {
            // 2Sum fold: cr -> s_, residue stays in cr
            #pragma unroll
            for (int p = 0; p < 4; ++p)
                #pragma unroll
                for (int i = 0; i < 4; ++i) {
                    float a = s_[p][i], b = cr[p][i];
                    float t1 = a + b;
                    float z  = t1 - a;
                    float e  = (a - (t1 - z)) + (b - z);
                    s_[p][i] = t1;
                    cr[p][i] = e;
                }
        }

        if (c < 63) {                              // split + store buf nxt
            uint32_t o1[2], o2[2];
            splitpairh(pa0.x, pa0.y, o1[0], o2[0]);
            splitpairh(pa0.z, pa0.w, o1[1], o2[1]);
            char* b0 = sm.tiles + (cur ^ 1) * BUF_BT + stOff;
            *(uint2*)(b0)           = make_uint2(o1[0], o1[1]);
            *(uint2*)(b0 + TERM_BT) = make_uint2(o2[0], o2[1]);
        }
        __syncthreads();
    }

    // ---- epilogue: combine K-halves into Cs (two barrier-ordered passes) ----
    const int r_ = lane >> 2;
    const int c2 = (lane & 3) * 2;
    if (wk == 0) {
        #pragma unroll
        for (int pj = 0; pj < 2; ++pj)
            #pragma unroll
            for (int t8 = 0; t8 < 2; ++t8) {
                const int p  = 2 * pj + t8;
                const int c0 = (2 * we + pj) * 16 + t8 * 8 + c2;
                sm.Cs[r_][c0]         = s_[p][0] + cr[p][0];
                sm.Cs[r_][c0 + 1]     = s_[p][1] + cr[p][1];
                sm.Cs[r_ + 8][c0]     = s_[p][2] + cr[p][2];
                sm.Cs[r_ + 8][c0 + 1] = s_[p][3] + cr[p][3];
            }
    }
    __syncthreads();
    if (wk == 1) {
        #pragma unroll
        for (int pj = 0; pj < 2; ++pj)
            #pragma unroll
            for (int t8 = 0; t8 < 2; ++t8) {
                const int p  = 2 * pj + t8;
                const int c0 = (2 * we + pj) * 16 + t8 * 8 + c2;
                sm.Cs[r_][c0]         += s_[p][0] + cr[p][0];
                sm.Cs[r_][c0 + 1]     += s_[p][1] + cr[p][1];
                sm.Cs[r_ + 8][c0]     += s_[p][2] + cr[p][2];
                sm.Cs[r_ + 8][c0 + 1] += s_[p][3] + cr[p][3];
            }
    }
    __syncthreads();

    // ---- top-8 per token via REDUX; each warp handles 4 tokens ----
    const float blo = bias[lane];
    const float bhi = bias[lane + 32];

    #pragma unroll 1
    for (int tt = 0; tt < 4; ++tt) {
        const int m   = wid * 4 + tt;
        const int tok = tok0 + m;
        const float v0 = sm.Cs[m][lane];
        const float v1 = sm.Cs[m][lane + 32];
        unsigned c0 = __float_as_uint(v0 + blo);
        unsigned c1 = __float_as_uint(v1 + bhi);
        unsigned u0 = c0 ^ (((int)c0 >> 31) | 0x80000000u);
        unsigned u1 = c1 ^ (((int)c1 >> 31) | 0x80000000u);

        int sel_i = 0;
        #pragma unroll
        for (int k = 0; k < 8; ++k) {
            unsigned cu; int ci;
            if (u1 > u0) { cu = u1; ci = lane + 32; }
            else         { cu = u0; ci = lane; }
            unsigned mx = __reduce_max_sync(0xffffffffu, cu);
            unsigned cand = (cu == mx) ? (unsigned)ci : 1000u;
            int wi = (int)__reduce_min_sync(0xffffffffu, cand);
            if (lane == k) sel_i = wi;
            if (wi < 32) { if (lane == wi)      u0 = 0u; }
            else         { if (lane == wi - 32) u1 = 0u; }
        }

        float p = 0.0f;
        if (lane < 8) {
            float raw = sm.Cs[m][sel_i];
            p = 1.0f / (1.0f + __expf(-raw));
        }
        float s = p;
        #pragma unroll
        for (int off = 4; off; off >>= 1) s += __shfl_xor_sync(0xffffffffu, s, off);
        s = fmaxf(s, 1e-12f);

        if (lane < 8) {
            out[(size_t)tok * 8 + lane]         = (float)sel_i;
            out[(size_t)w_off + tok * 8 + lane] = p / s;
        }
    }
}

extern "C" void kernel_launch(void* const* d_in, const int* in_sizes, int n_in,
                              void* d_out, int out_size) {
    const float* X    = (const float*)d_in[0];
    const float* W    = (const float*)d_in[1];
    const float* bias = (const float*)d_in[2];
    float* out = (float*)d_out;

    const int T = in_sizes[0] / 2048;   // 16384 tokens
    const int w_off = out_size >> 1;

    w_split_kernel<<<64, 256>>>(W);
    moe_gate_mma<<<T / 16, 128>>>(X, bias, out, w_off);
}